// round 16
// baseline (speedup 1.0000x reference)
#include <cuda_runtime.h>
#include <cuda_bf16.h>
#include <cuda_fp16.h>
#include <cstdint>

#define B_USERS 2048
#define P_POSTS 16384
#define LEN     50
#define D_EMB   300
#define NFILT   100
#define HID     64
#define INF_    768

#define DC16    19             // ceil(300/16) k-chunks of 16
#define WROWS   52             // 48 positions + max kk shift 4
#define WSTRIDE 156            // words per row; 156%32=28 -> ldmatrix conflict-free
#define USZ     (WROWS * WSTRIDE)   // 8112 words per user

// fragment counts (13 n8 tiles per group)
#define FRG0    (13 * 3 * DC16)     // 741
#define FRG1    (13 * 4 * DC16)     // 988
#define FRG2    (13 * 5 * DC16)     // 1235
#define NFRAG   (FRG0 + FRG1 + FRG2)  // 2964

// ---------------- scratch (device globals; no allocation) ----------------
__device__ int    g_segstart[B_USERS + 1];
__device__ uint4  g_hq[(size_t)B_USERS * USZ / 4];    // packed fp16 hist, conv layout
__device__ float  g_rec[B_USERS * HID];
__device__ uint2  g_wf[NFRAG * 32];     // W frags: {b0, b1} fp16x2 per lane
__device__ float  g_hwt[300 * 64];      // hist_w transposed [j][o]
__device__ float  g_w1t[INF_ * 128];    // fc_w1 transposed [d][o]
__device__ float  g_w2t[128 * 64];      // fc_w2 transposed [d][j]

// ---------------- job table: 8 warps, cnt<=2 (proven config) ----------------
struct Job { int8_t g, nb0, cnt; };
__constant__ Job c_slots[8][4] = {
    {{2, 0,2},{2, 2,2},{-1,0,0},{-1,0,0}},
    {{2, 4,2},{2, 6,2},{-1,0,0},{-1,0,0}},
    {{2, 8,2},{2,10,2},{-1,0,0},{-1,0,0}},
    {{2,12,1},{1, 0,2},{0, 0,2},{-1,0,0}},
    {{1, 2,2},{1, 4,2},{0, 2,1},{-1,0,0}},
    {{1, 6,2},{1, 8,2},{0, 3,1},{-1,0,0}},
    {{1,10,2},{1,12,1},{0, 4,2},{0, 6,1}},
    {{0, 7,2},{0, 9,2},{0,11,2},{-1,0,0}},
};

__device__ __forceinline__ uint32_t pack_h2(float a, float b) {
    __half ha = __float2half_rn(a);
    __half hb = __float2half_rn(b);
    return ((uint32_t)__half_as_ushort(hb) << 16) | __half_as_ushort(ha);
}

#define MMA_F16(c, a, b0, b1)                                                   \
    asm("mma.sync.aligned.m16n8k16.row.col.f32.f16.f16.f32 "                    \
        "{%0,%1,%2,%3},{%4,%5,%6,%7},{%8,%9},{%0,%1,%2,%3};"                    \
        : "+f"(c[0]), "+f"(c[1]), "+f"(c[2]), "+f"(c[3])                         \
        : "r"(a[0]), "r"(a[1]), "r"(a[2]), "r"(a[3]), "r"(b0), "r"(b1))

__device__ __forceinline__ void ldsm4(uint32_t* r, const uint32_t* p) {
    uint32_t addr = (uint32_t)__cvta_generic_to_shared(p);
    asm volatile("ldmatrix.sync.aligned.m8n8.x4.shared.b16 {%0,%1,%2,%3}, [%4];"
                 : "=r"(r[0]), "=r"(r[1]), "=r"(r[2]), "=r"(r[3]) : "r"(addr));
}

// ---------------- kernel A: segment offsets ----------------
__global__ void seg_bounds_kernel(const int* __restrict__ seg_ids) {
    int b = blockIdx.x * blockDim.x + threadIdx.x;
    if (b > B_USERS) return;
    int lo = 0, hi = P_POSTS;
    while (lo < hi) {
        int mid = (lo + hi) >> 1;
        if (seg_ids[mid] < b) lo = mid + 1; else hi = mid;
    }
    g_segstart[b] = lo;
}

// ---------------- prep: fp16 W fragments + small transposes ----------------
__global__ void prep_kernel(const float* __restrict__ w3, const float* __restrict__ w4,
                            const float* __restrict__ w5, const float* __restrict__ hw_,
                            const float* __restrict__ w1, const float* __restrict__ w2) {
    int idx = blockIdx.x * 256 + threadIdx.x;
    if (idx < NFRAG * 32) {
        int lane = idx & 31;
        int frag = idx >> 5;
        int Kg; const float* w; int rel;
        if (frag < FRG0)               { Kg = 3; w = w3; rel = frag; }
        else if (frag < FRG0 + FRG1)   { Kg = 4; w = w4; rel = frag - FRG0; }
        else                           { Kg = 5; w = w5; rel = frag - FRG0 - FRG1; }
        int nb = rel / (Kg * DC16);
        int r2 = rel - nb * (Kg * DC16);
        int kk = r2 / DC16;
        int dc = r2 - kk * DC16;
        int n  = lane >> 2;
        int t  = lane & 3;
        int f  = nb * 8 + n;
        float v[4] = {0.f, 0.f, 0.f, 0.f};
        int dk[4] = {2*t, 2*t+1, 2*t+8, 2*t+9};
        if (f < NFILT) {
#pragma unroll
            for (int e = 0; e < 4; ++e) {
                int d = dc * 16 + dk[e];
                if (d < D_EMB) v[e] = __ldg(w + (f * D_EMB + d) * Kg + kk);
            }
        }
        uint2 out;
        out.x = pack_h2(v[0], v[1]);
        out.y = pack_h2(v[2], v[3]);
        g_wf[frag * 32 + lane] = out;
        return;
    }
    int i2 = idx - NFRAG * 32;                 // g_hwt: 300*64
    if (i2 >= 0 && i2 < 300 * 64) {
        int o = i2 & 63; int j = i2 >> 6;
        g_hwt[i2] = __ldg(hw_ + o * 300 + j);
        return;
    }
    int i3 = i2 - 300 * 64;                    // g_w1t: 768*128
    if (i3 >= 0 && i3 < INF_ * 128) {
        int o = i3 & 127; int d = i3 >> 7;
        g_w1t[i3] = __ldg(w1 + o * INF_ + d);
        return;
    }
    int i4 = i3 - INF_ * 128;                  // g_w2t: 128*64
    if (i4 >= 0 && i4 < 128 * 64) {
        int j = i4 & 63; int d = i4 >> 6;
        g_w2t[i4] = __ldg(w2 + j * 128 + d);
    }
}

// ---------------- kernel B: segment-mean -> packed fp16, conv layout ----------------
__global__ void __launch_bounds__(96)
hist_kernel(const int* __restrict__ tokens, const float* __restrict__ emb) {
    int l = blockIdx.x;
    int b = blockIdx.y;
    int t = threadIdx.x;
    uint2* hq = (uint2*)g_hq;
    size_t rowbase = ((size_t)b * USZ + l * WSTRIDE) >> 1;   // uint2 index

    if (l >= LEN) {                            // pad rows: zero all 156 words
        if (t < WSTRIDE / 2) hq[rowbase + t] = make_uint2(0u, 0u);
        return;
    }
    if (t >= 75) {                             // pad words 150..155
        if (t < 78) hq[rowbase + t] = make_uint2(0u, 0u);
        return;
    }

    int s = g_segstart[b], e = g_segstart[b + 1];
    float4 a = {0.f, 0.f, 0.f, 0.f};
    float4 c = {0.f, 0.f, 0.f, 0.f};
    int p = s;
    for (; p + 3 < e; p += 4) {
        int t0 = __ldg(tokens + p * LEN + l);
        int t1 = __ldg(tokens + (p + 1) * LEN + l);
        int t2 = __ldg(tokens + (p + 2) * LEN + l);
        int t3 = __ldg(tokens + (p + 3) * LEN + l);
        float4 v0 = __ldg((const float4*)(emb + (size_t)t0 * D_EMB) + t);
        float4 v1 = __ldg((const float4*)(emb + (size_t)t1 * D_EMB) + t);
        float4 v2 = __ldg((const float4*)(emb + (size_t)t2 * D_EMB) + t);
        float4 v3 = __ldg((const float4*)(emb + (size_t)t3 * D_EMB) + t);
        a.x += v0.x + v2.x; a.y += v0.y + v2.y; a.z += v0.z + v2.z; a.w += v0.w + v2.w;
        c.x += v1.x + v3.x; c.y += v1.y + v3.y; c.z += v1.z + v3.z; c.w += v1.w + v3.w;
    }
    for (; p < e; ++p) {
        int t0 = __ldg(tokens + p * LEN + l);
        float4 v0 = __ldg((const float4*)(emb + (size_t)t0 * D_EMB) + t);
        a.x += v0.x; a.y += v0.y; a.z += v0.z; a.w += v0.w;
    }
    float sc = 1.0f / (float)max(e - s, 1);
    uint2 w;
    w.x = pack_h2((a.x + c.x) * sc, (a.y + c.y) * sc);
    w.y = pack_h2((a.z + c.z) * sc, (a.w + c.w) * sc);
    hq[rowbase + t] = w;
}

// ---------------- conv job: fp16 mma, depth-2 weight pipeline ----------------
template <int CNT>
__device__ __forceinline__ void conv_job(const uint32_t* __restrict__ shq,
                                         int Kg, int gbase, int nb0, int Tg,
                                         const float* __restrict__ bp,
                                         float* __restrict__ sf) {
    int lane = threadIdx.x & 31;
    int g8   = lane >> 2;
    int t    = lane & 3;
    int lr     = lane & 7;
    int sel    = lane >> 3;
    int rowsel = lr + ((sel & 1) << 3);
    int colsel = (sel & 2) << 1;

    float acc[3][CNT][4];
#pragma unroll
    for (int mt = 0; mt < 3; ++mt)
#pragma unroll
        for (int j = 0; j < CNT; ++j)
#pragma unroll
            for (int c = 0; c < 4; ++c) acc[mt][j][c] = 0.f;

    for (int kk = 0; kk < Kg; ++kk) {
        const uint2* fptr = g_wf + (size_t)(gbase + (nb0 * Kg + kk) * DC16) * 32 + lane;
        const size_t jstride = (size_t)(Kg * DC16) * 32;
        int rbase = kk + rowsel;

        // depth-2 software pipeline on the L2-resident weight stream
        uint2 wv[CNT], wn[CNT];
#pragma unroll
        for (int j = 0; j < CNT; ++j) wv[j] = __ldg(fptr + j * jstride);
#pragma unroll
        for (int j = 0; j < CNT; ++j) wn[j] = __ldg(fptr + j * jstride + 32);

        for (int dc = 0; dc < DC16; ++dc) {
            uint2 w2[CNT];
            if (dc + 2 < DC16) {
#pragma unroll
                for (int j = 0; j < CNT; ++j)
                    w2[j] = __ldg(fptr + j * jstride + (dc + 2) * 32);
            }
            uint32_t ah[3][4];
            int widx = dc * 8 + colsel;
#pragma unroll
            for (int mt = 0; mt < 3; ++mt)
                ldsm4(ah[mt], shq + (mt * 16 + rbase) * WSTRIDE + widx);
#pragma unroll
            for (int j = 0; j < CNT; ++j)
#pragma unroll
                for (int mt = 0; mt < 3; ++mt)
                    MMA_F16(acc[mt][j], ah[mt], wv[j].x, wv[j].y);
#pragma unroll
            for (int j = 0; j < CNT; ++j) { wv[j] = wn[j]; wn[j] = w2[j]; }
        }
    }

#pragma unroll
    for (int j = 0; j < CNT; ++j) {
        float m0 = -1e30f, m1 = -1e30f;
#pragma unroll
        for (int mt = 0; mt < 3; ++mt) {
            int p0 = mt * 16 + g8;
            int p1 = p0 + 8;
            if (p0 < Tg) { m0 = fmaxf(m0, acc[mt][j][0]); m1 = fmaxf(m1, acc[mt][j][1]); }
            if (p1 < Tg) { m0 = fmaxf(m0, acc[mt][j][2]); m1 = fmaxf(m1, acc[mt][j][3]); }
        }
#pragma unroll
        for (int off = 4; off < 32; off <<= 1) {
            m0 = fmaxf(m0, __shfl_xor_sync(0xffffffff, m0, off));
            m1 = fmaxf(m1, __shfl_xor_sync(0xffffffff, m1, off));
        }
        if (g8 == 0) {
            int f0 = (nb0 + j) * 8 + 2 * t;
            if (f0 < NFILT)     sf[f0]     = fmaxf(m0 + __ldg(bp + f0), 0.f);
            if (f0 + 1 < NFILT) sf[f0 + 1] = fmaxf(m1 + __ldg(bp + f0 + 1), 0.f);
        }
    }
}

__device__ __forceinline__ void run_job(const uint32_t* shq,
                                        int g, int nb0, int cnt,
                                        const float* b3, const float* b4,
                                        const float* b5, float* feats_u) {
    int Kg = 3 + g;
    int gbase = (g == 0) ? 0 : ((g == 1) ? FRG0 : (FRG0 + FRG1));
    int Tg = 51 - Kg;
    const float* bp = (g == 0) ? b3 : ((g == 1) ? b4 : b5);
    float* sf = feats_u + g * 100;
    if (cnt == 2) conv_job<2>(shq, Kg, gbase, nb0, Tg, bp, sf);
    else          conv_job<1>(shq, Kg, gbase, nb0, Tg, bp, sf);
}

// ---------------- kernel C: TextCNN via fp16 tensor cores, 1 user / 256 thr / occ 4 ----------------
__global__ void __launch_bounds__(256, 4)
conv_mma_kernel(const float* __restrict__ b3, const float* __restrict__ b4,
                const float* __restrict__ b5, const float* __restrict__ hb_) {
    extern __shared__ uint32_t shw[];           // [hq USZ][feats 304]
    float* feats = (float*)(shw + USZ);
    int tid = threadIdx.x;
    int b   = blockIdx.x;

    {
        uint4* dq = (uint4*)shw;
        const uint4* sq = g_hq + (size_t)b * (USZ / 4);
        for (int i = tid; i < USZ / 4; i += 256) dq[i] = __ldg(sq + i);
    }
    __syncthreads();

    int slot = tid >> 5;
#pragma unroll
    for (int q = 0; q < 4; ++q) {
        Job jb = c_slots[slot][q];
        if (jb.g < 0) continue;
        run_job(shw, jb.g, jb.nb0, jb.cnt, b3, b4, b5, feats);
    }
    __syncthreads();

    // rec GEMM: [300 feats] x [64 outs]
    if (tid < 64) {
        int o = tid;
        float r = __ldg(hb_ + o);
#pragma unroll 4
        for (int j = 0; j < 300; ++j)
            r = fmaf(feats[j], __ldg(g_hwt + j * HID + o), r);
        g_rec[b * HID + o] = r;
    }
}

// ---------------- kernel D: fc_out on root features + final add (TB=8) ----------------
#define TB 8
__global__ void __launch_bounds__(256)
fc_kernel(const float* __restrict__ x, const int* __restrict__ root,
          const float* __restrict__ b1, const float* __restrict__ b2,
          float* __restrict__ out) {
    __shared__ float sx[TB * INF_];
    __shared__ float hh[TB * 128];
    __shared__ int   ridx[TB];
    int tid = threadIdx.x;
    int b0 = blockIdx.x * TB;

    if (tid < TB) ridx[tid] = __ldg(root + b0 + tid);
    __syncthreads();
    for (int i = tid; i < TB * INF_; i += 256) {
        int u = i / INF_; int d = i - u * INF_;
        sx[i] = __ldg(x + (size_t)ridx[u] * INF_ + d);
    }
    __syncthreads();

    {
        int o  = tid & 127;
        int ug = tid >> 7;
        float acc[4] = {0.f, 0.f, 0.f, 0.f};
        for (int d = 0; d < INF_; ++d) {
            float wv = __ldg(g_w1t + d * 128 + o);
#pragma unroll
            for (int uu = 0; uu < 4; ++uu)
                acc[uu] = fmaf(sx[(ug * 4 + uu) * INF_ + d], wv, acc[uu]);
        }
        float bb = __ldg(b1 + o);
#pragma unroll
        for (int uu = 0; uu < 4; ++uu)
            hh[(ug * 4 + uu) * 128 + o] = fmaxf(acc[uu] + bb, 0.f);
    }
    __syncthreads();

    {
        int j = tid & 63;
        int q = tid >> 6;
        int u0 = 2 * q, u1 = 2 * q + 1;
        float a0 = 0.f, a1 = 0.f;
        for (int d = 0; d < 128; ++d) {
            float wv = __ldg(g_w2t + d * 64 + j);
            a0 = fmaf(hh[u0 * 128 + d], wv, a0);
            a1 = fmaf(hh[u1 * 128 + d], wv, a1);
        }
        float bb = __ldg(b2 + j);
        out[(b0 + u0) * HID + j] = a0 + bb + g_rec[(b0 + u0) * HID + j];
        out[(b0 + u1) * HID + j] = a1 + bb + g_rec[(b0 + u1) * HID + j];
    }
}

// ---------------- launch (sequential; overlap proved neutral) ----------------
extern "C" void kernel_launch(void* const* d_in, const int* in_sizes, int n_in,
                              void* d_out, int out_size) {
    const float* x        = (const float*)d_in[0];
    const int*   root     = (const int*)  d_in[1];
    const int*   tokens   = (const int*)  d_in[2];
    const int*   seg_ids  = (const int*)  d_in[3];
    const float* emb      = (const float*)d_in[4];
    const float* w3 = (const float*)d_in[5];   const float* b3 = (const float*)d_in[6];
    const float* w4 = (const float*)d_in[7];   const float* b4 = (const float*)d_in[8];
    const float* w5 = (const float*)d_in[9];   const float* b5 = (const float*)d_in[10];
    const float* hw = (const float*)d_in[11];  const float* hb = (const float*)d_in[12];
    const float* f1w = (const float*)d_in[13]; const float* f1b = (const float*)d_in[14];
    const float* f2w = (const float*)d_in[15]; const float* f2b = (const float*)d_in[16];
    float* out = (float*)d_out;

    const int conv_smem = (USZ + 304) * (int)sizeof(uint32_t);  // ~33.7 KB
    cudaFuncSetAttribute(conv_mma_kernel, cudaFuncAttributeMaxDynamicSharedMemorySize,
                         conv_smem);

    int prep_threads = NFRAG * 32 + 300 * 64 + INF_ * 128 + 128 * 64;
    seg_bounds_kernel<<<(B_USERS + 1 + 255) / 256, 256>>>(seg_ids);
    prep_kernel<<<(prep_threads + 255) / 256, 256>>>(w3, w4, w5, hw, f1w, f2w);
    {
        dim3 grid(WROWS, B_USERS);               // 52 rows: 50 data + 2 pad
        hist_kernel<<<grid, 96>>>(tokens, emb);
    }
    conv_mma_kernel<<<B_USERS, 256, conv_smem>>>(b3, b4, b5, hb);
    fc_kernel<<<B_USERS / TB, 256>>>(x, root, f1b, f2b, out);
}

// round 17
// speedup vs baseline: 1.0817x; 1.0817x over previous
#include <cuda_runtime.h>
#include <cuda_bf16.h>
#include <cuda_fp16.h>
#include <cstdint>

#define B_USERS 2048
#define P_POSTS 16384
#define LEN     50
#define D_EMB   300
#define NFILT   100
#define HID     64
#define INF_    768

#define DC16    19             // ceil(300/16) k-chunks of 16
#define WROWS   52             // 48 positions + max kk shift 4
#define WSTRIDE 156            // words per row; 156%32=28 -> ldmatrix conflict-free
#define USZ     (WROWS * WSTRIDE)   // 8112 words per user

// fragment counts (13 n8 tiles per group)
#define FRG0    (13 * 3 * DC16)     // 741
#define FRG1    (13 * 4 * DC16)     // 988
#define FRG2    (13 * 5 * DC16)     // 1235
#define NFRAG   (FRG0 + FRG1 + FRG2)  // 2964

// ---------------- scratch (device globals; no allocation) ----------------
__device__ int    g_segstart[B_USERS + 1];
__device__ uint4  g_hq[(size_t)B_USERS * USZ / 4];    // packed fp16 hist, conv layout
__device__ float  g_rec[B_USERS * HID];
__device__ uint2  g_wf[NFRAG * 32];     // W frags: {b0, b1} fp16x2 per lane
__device__ float  g_hwt[300 * 64];      // hist_w transposed [j][o]
__device__ float  g_w1t[INF_ * 128];    // fc_w1 transposed [d][o]
__device__ float  g_w2t[128 * 64];      // fc_w2 transposed [d][j]

// ---------------- job table: 8 warps, cnt<=2 (proven config) ----------------
struct Job { int8_t g, nb0, cnt; };
__constant__ Job c_slots[8][4] = {
    {{2, 0,2},{2, 2,2},{-1,0,0},{-1,0,0}},
    {{2, 4,2},{2, 6,2},{-1,0,0},{-1,0,0}},
    {{2, 8,2},{2,10,2},{-1,0,0},{-1,0,0}},
    {{2,12,1},{1, 0,2},{0, 0,2},{-1,0,0}},
    {{1, 2,2},{1, 4,2},{0, 2,1},{-1,0,0}},
    {{1, 6,2},{1, 8,2},{0, 3,1},{-1,0,0}},
    {{1,10,2},{1,12,1},{0, 4,2},{0, 6,1}},
    {{0, 7,2},{0, 9,2},{0,11,2},{-1,0,0}},
};

__device__ __forceinline__ uint32_t pack_h2(float a, float b) {
    __half ha = __float2half_rn(a);
    __half hb = __float2half_rn(b);
    return ((uint32_t)__half_as_ushort(hb) << 16) | __half_as_ushort(ha);
}

#define MMA_F16(c, a, b0, b1)                                                   \
    asm("mma.sync.aligned.m16n8k16.row.col.f32.f16.f16.f32 "                    \
        "{%0,%1,%2,%3},{%4,%5,%6,%7},{%8,%9},{%0,%1,%2,%3};"                    \
        : "+f"(c[0]), "+f"(c[1]), "+f"(c[2]), "+f"(c[3])                         \
        : "r"(a[0]), "r"(a[1]), "r"(a[2]), "r"(a[3]), "r"(b0), "r"(b1))

__device__ __forceinline__ void ldsm4(uint32_t* r, const uint32_t* p) {
    uint32_t addr = (uint32_t)__cvta_generic_to_shared(p);
    asm volatile("ldmatrix.sync.aligned.m8n8.x4.shared.b16 {%0,%1,%2,%3}, [%4];"
                 : "=r"(r[0]), "=r"(r[1]), "=r"(r[2]), "=r"(r[3]) : "r"(addr));
}

// ---------------- kernel A: segment offsets ----------------
__global__ void seg_bounds_kernel(const int* __restrict__ seg_ids) {
    int b = blockIdx.x * blockDim.x + threadIdx.x;
    if (b > B_USERS) return;
    int lo = 0, hi = P_POSTS;
    while (lo < hi) {
        int mid = (lo + hi) >> 1;
        if (seg_ids[mid] < b) lo = mid + 1; else hi = mid;
    }
    g_segstart[b] = lo;
}

// ---------------- prep: fp16 W fragments + small transposes ----------------
__global__ void prep_kernel(const float* __restrict__ w3, const float* __restrict__ w4,
                            const float* __restrict__ w5, const float* __restrict__ hw_,
                            const float* __restrict__ w1, const float* __restrict__ w2) {
    int idx = blockIdx.x * 256 + threadIdx.x;
    if (idx < NFRAG * 32) {
        int lane = idx & 31;
        int frag = idx >> 5;
        int Kg; const float* w; int rel;
        if (frag < FRG0)               { Kg = 3; w = w3; rel = frag; }
        else if (frag < FRG0 + FRG1)   { Kg = 4; w = w4; rel = frag - FRG0; }
        else                           { Kg = 5; w = w5; rel = frag - FRG0 - FRG1; }
        int nb = rel / (Kg * DC16);
        int r2 = rel - nb * (Kg * DC16);
        int kk = r2 / DC16;
        int dc = r2 - kk * DC16;
        int n  = lane >> 2;
        int t  = lane & 3;
        int f  = nb * 8 + n;
        float v[4] = {0.f, 0.f, 0.f, 0.f};
        int dk[4] = {2*t, 2*t+1, 2*t+8, 2*t+9};
        if (f < NFILT) {
#pragma unroll
            for (int e = 0; e < 4; ++e) {
                int d = dc * 16 + dk[e];
                if (d < D_EMB) v[e] = __ldg(w + (f * D_EMB + d) * Kg + kk);
            }
        }
        uint2 out;
        out.x = pack_h2(v[0], v[1]);
        out.y = pack_h2(v[2], v[3]);
        g_wf[frag * 32 + lane] = out;
        return;
    }
    int i2 = idx - NFRAG * 32;                 // g_hwt: 300*64
    if (i2 >= 0 && i2 < 300 * 64) {
        int o = i2 & 63; int j = i2 >> 6;
        g_hwt[i2] = __ldg(hw_ + o * 300 + j);
        return;
    }
    int i3 = i2 - 300 * 64;                    // g_w1t: 768*128
    if (i3 >= 0 && i3 < INF_ * 128) {
        int o = i3 & 127; int d = i3 >> 7;
        g_w1t[i3] = __ldg(w1 + o * INF_ + d);
        return;
    }
    int i4 = i3 - INF_ * 128;                  // g_w2t: 128*64
    if (i4 >= 0 && i4 < 128 * 64) {
        int j = i4 & 63; int d = i4 >> 6;
        g_w2t[i4] = __ldg(w2 + j * 128 + d);
    }
}

// ---------------- kernel B: segment-mean -> packed fp16, conv layout ----------------
__global__ void __launch_bounds__(96)
hist_kernel(const int* __restrict__ tokens, const float* __restrict__ emb) {
    int l = blockIdx.x;
    int b = blockIdx.y;
    int t = threadIdx.x;
    uint2* hq = (uint2*)g_hq;
    size_t rowbase = ((size_t)b * USZ + l * WSTRIDE) >> 1;   // uint2 index

    if (l >= LEN) {                            // pad rows: zero all 156 words
        if (t < WSTRIDE / 2) hq[rowbase + t] = make_uint2(0u, 0u);
        return;
    }
    if (t >= 75) {                             // pad words 150..155
        if (t < 78) hq[rowbase + t] = make_uint2(0u, 0u);
        return;
    }

    int s = g_segstart[b], e = g_segstart[b + 1];
    float4 a = {0.f, 0.f, 0.f, 0.f};
    float4 c = {0.f, 0.f, 0.f, 0.f};
    int p = s;
    for (; p + 3 < e; p += 4) {
        int t0 = __ldg(tokens + p * LEN + l);
        int t1 = __ldg(tokens + (p + 1) * LEN + l);
        int t2 = __ldg(tokens + (p + 2) * LEN + l);
        int t3 = __ldg(tokens + (p + 3) * LEN + l);
        float4 v0 = __ldg((const float4*)(emb + (size_t)t0 * D_EMB) + t);
        float4 v1 = __ldg((const float4*)(emb + (size_t)t1 * D_EMB) + t);
        float4 v2 = __ldg((const float4*)(emb + (size_t)t2 * D_EMB) + t);
        float4 v3 = __ldg((const float4*)(emb + (size_t)t3 * D_EMB) + t);
        a.x += v0.x + v2.x; a.y += v0.y + v2.y; a.z += v0.z + v2.z; a.w += v0.w + v2.w;
        c.x += v1.x + v3.x; c.y += v1.y + v3.y; c.z += v1.z + v3.z; c.w += v1.w + v3.w;
    }
    for (; p < e; ++p) {
        int t0 = __ldg(tokens + p * LEN + l);
        float4 v0 = __ldg((const float4*)(emb + (size_t)t0 * D_EMB) + t);
        a.x += v0.x; a.y += v0.y; a.z += v0.z; a.w += v0.w;
    }
    float sc = 1.0f / (float)max(e - s, 1);
    uint2 w;
    w.x = pack_h2((a.x + c.x) * sc, (a.y + c.y) * sc);
    w.y = pack_h2((a.z + c.z) * sc, (a.w + c.w) * sc);
    hq[rowbase + t] = w;
}

// ---------------- conv job: fp16 mma, double-buffered A frags + depth-1 W prefetch ----------------
template <int CNT>
__device__ __forceinline__ void conv_job(const uint32_t* __restrict__ shq,
                                         int Kg, int gbase, int nb0, int Tg,
                                         const float* __restrict__ bp,
                                         float* __restrict__ sf) {
    int lane = threadIdx.x & 31;
    int g8   = lane >> 2;
    int t    = lane & 3;
    int lr     = lane & 7;
    int sel    = lane >> 3;
    int rowsel = lr + ((sel & 1) << 3);
    int colsel = (sel & 2) << 1;

    float acc[3][CNT][4];
#pragma unroll
    for (int mt = 0; mt < 3; ++mt)
#pragma unroll
        for (int j = 0; j < CNT; ++j)
#pragma unroll
            for (int c = 0; c < 4; ++c) acc[mt][j][c] = 0.f;

    for (int kk = 0; kk < Kg; ++kk) {
        const uint2* fptr = g_wf + (size_t)(gbase + (nb0 * Kg + kk) * DC16) * 32 + lane;
        const size_t jstride = (size_t)(Kg * DC16) * 32;
        const uint32_t* abase = shq + (kk + rowsel) * WSTRIDE + colsel;

        uint2 wv[CNT], wn[CNT];
        uint32_t ah[2][3][4];                  // ping-pong A fragments
#pragma unroll
        for (int j = 0; j < CNT; ++j) wv[j] = __ldg(fptr + j * jstride);
#pragma unroll
        for (int mt = 0; mt < 3; ++mt)
            ldsm4(ah[0][mt], abase + mt * 16 * WSTRIDE);

        for (int dc = 0; dc < DC16; ++dc) {
            int cur = dc & 1, nxt = cur ^ 1;
            if (dc + 1 < DC16) {
#pragma unroll
                for (int j = 0; j < CNT; ++j)
                    wn[j] = __ldg(fptr + j * jstride + (dc + 1) * 32);
#pragma unroll
                for (int mt = 0; mt < 3; ++mt)
                    ldsm4(ah[nxt][mt], abase + mt * 16 * WSTRIDE + (dc + 1) * 8);
            }
#pragma unroll
            for (int j = 0; j < CNT; ++j)
#pragma unroll
                for (int mt = 0; mt < 3; ++mt)
                    MMA_F16(acc[mt][j], ah[cur][mt], wv[j].x, wv[j].y);
#pragma unroll
            for (int j = 0; j < CNT; ++j) wv[j] = wn[j];
        }
    }

#pragma unroll
    for (int j = 0; j < CNT; ++j) {
        float m0 = -1e30f, m1 = -1e30f;
#pragma unroll
        for (int mt = 0; mt < 3; ++mt) {
            int p0 = mt * 16 + g8;
            int p1 = p0 + 8;
            if (p0 < Tg) { m0 = fmaxf(m0, acc[mt][j][0]); m1 = fmaxf(m1, acc[mt][j][1]); }
            if (p1 < Tg) { m0 = fmaxf(m0, acc[mt][j][2]); m1 = fmaxf(m1, acc[mt][j][3]); }
        }
#pragma unroll
        for (int off = 4; off < 32; off <<= 1) {
            m0 = fmaxf(m0, __shfl_xor_sync(0xffffffff, m0, off));
            m1 = fmaxf(m1, __shfl_xor_sync(0xffffffff, m1, off));
        }
        if (g8 == 0) {
            int f0 = (nb0 + j) * 8 + 2 * t;
            if (f0 < NFILT)     sf[f0]     = fmaxf(m0 + __ldg(bp + f0), 0.f);
            if (f0 + 1 < NFILT) sf[f0 + 1] = fmaxf(m1 + __ldg(bp + f0 + 1), 0.f);
        }
    }
}

__device__ __forceinline__ void run_job(const uint32_t* shq,
                                        int g, int nb0, int cnt,
                                        const float* b3, const float* b4,
                                        const float* b5, float* feats_u) {
    int Kg = 3 + g;
    int gbase = (g == 0) ? 0 : ((g == 1) ? FRG0 : (FRG0 + FRG1));
    int Tg = 51 - Kg;
    const float* bp = (g == 0) ? b3 : ((g == 1) ? b4 : b5);
    float* sf = feats_u + g * 100;
    if (cnt == 2) conv_job<2>(shq, Kg, gbase, nb0, Tg, bp, sf);
    else          conv_job<1>(shq, Kg, gbase, nb0, Tg, bp, sf);
}

// ---------------- kernel C: TextCNN fp16 mma, double-buffered, occ 3 ----------------
__global__ void __launch_bounds__(256, 3)
conv_mma_kernel(const float* __restrict__ b3, const float* __restrict__ b4,
                const float* __restrict__ b5, const float* __restrict__ hb_) {
    extern __shared__ uint32_t shw[];           // [hq USZ][feats 304]
    float* feats = (float*)(shw + USZ);
    int tid = threadIdx.x;
    int b   = blockIdx.x;

    {
        uint4* dq = (uint4*)shw;
        const uint4* sq = g_hq + (size_t)b * (USZ / 4);
        for (int i = tid; i < USZ / 4; i += 256) dq[i] = __ldg(sq + i);
    }
    __syncthreads();

    int slot = tid >> 5;
#pragma unroll
    for (int q = 0; q < 4; ++q) {
        Job jb = c_slots[slot][q];
        if (jb.g < 0) continue;
        run_job(shw, jb.g, jb.nb0, jb.cnt, b3, b4, b5, feats);
    }
    __syncthreads();

    // rec GEMM: [300 feats] x [64 outs]
    if (tid < 64) {
        int o = tid;
        float r = __ldg(hb_ + o);
#pragma unroll 4
        for (int j = 0; j < 300; ++j)
            r = fmaf(feats[j], __ldg(g_hwt + j * HID + o), r);
        g_rec[b * HID + o] = r;
    }
}

// ---------------- kernel D: fc_out on root features + final add (TB=8) ----------------
#define TB 8
__global__ void __launch_bounds__(256)
fc_kernel(const float* __restrict__ x, const int* __restrict__ root,
          const float* __restrict__ b1, const float* __restrict__ b2,
          float* __restrict__ out) {
    __shared__ float sx[TB * INF_];
    __shared__ float hh[TB * 128];
    __shared__ int   ridx[TB];
    int tid = threadIdx.x;
    int b0 = blockIdx.x * TB;

    if (tid < TB) ridx[tid] = __ldg(root + b0 + tid);
    __syncthreads();
    for (int i = tid; i < TB * INF_; i += 256) {
        int u = i / INF_; int d = i - u * INF_;
        sx[i] = __ldg(x + (size_t)ridx[u] * INF_ + d);
    }
    __syncthreads();

    {
        int o  = tid & 127;
        int ug = tid >> 7;
        float acc[4] = {0.f, 0.f, 0.f, 0.f};
        for (int d = 0; d < INF_; ++d) {
            float wv = __ldg(g_w1t + d * 128 + o);
#pragma unroll
            for (int uu = 0; uu < 4; ++uu)
                acc[uu] = fmaf(sx[(ug * 4 + uu) * INF_ + d], wv, acc[uu]);
        }
        float bb = __ldg(b1 + o);
#pragma unroll
        for (int uu = 0; uu < 4; ++uu)
            hh[(ug * 4 + uu) * 128 + o] = fmaxf(acc[uu] + bb, 0.f);
    }
    __syncthreads();

    {
        int j = tid & 63;
        int q = tid >> 6;
        int u0 = 2 * q, u1 = 2 * q + 1;
        float a0 = 0.f, a1 = 0.f;
        for (int d = 0; d < 128; ++d) {
            float wv = __ldg(g_w2t + d * 64 + j);
            a0 = fmaf(hh[u0 * 128 + d], wv, a0);
            a1 = fmaf(hh[u1 * 128 + d], wv, a1);
        }
        float bb = __ldg(b2 + j);
        out[(b0 + u0) * HID + j] = a0 + bb + g_rec[(b0 + u0) * HID + j];
        out[(b0 + u1) * HID + j] = a1 + bb + g_rec[(b0 + u1) * HID + j];
    }
}

// ---------------- launch (sequential) ----------------
extern "C" void kernel_launch(void* const* d_in, const int* in_sizes, int n_in,
                              void* d_out, int out_size) {
    const float* x        = (const float*)d_in[0];
    const int*   root     = (const int*)  d_in[1];
    const int*   tokens   = (const int*)  d_in[2];
    const int*   seg_ids  = (const int*)  d_in[3];
    const float* emb      = (const float*)d_in[4];
    const float* w3 = (const float*)d_in[5];   const float* b3 = (const float*)d_in[6];
    const float* w4 = (const float*)d_in[7];   const float* b4 = (const float*)d_in[8];
    const float* w5 = (const float*)d_in[9];   const float* b5 = (const float*)d_in[10];
    const float* hw = (const float*)d_in[11];  const float* hb = (const float*)d_in[12];
    const float* f1w = (const float*)d_in[13]; const float* f1b = (const float*)d_in[14];
    const float* f2w = (const float*)d_in[15]; const float* f2b = (const float*)d_in[16];
    float* out = (float*)d_out;

    const int conv_smem = (USZ + 304) * (int)sizeof(uint32_t);  // ~33.7 KB
    cudaFuncSetAttribute(conv_mma_kernel, cudaFuncAttributeMaxDynamicSharedMemorySize,
                         conv_smem);

    int prep_threads = NFRAG * 32 + 300 * 64 + INF_ * 128 + 128 * 64;
    seg_bounds_kernel<<<(B_USERS + 1 + 255) / 256, 256>>>(seg_ids);
    prep_kernel<<<(prep_threads + 255) / 256, 256>>>(w3, w4, w5, hw, f1w, f2w);
    {
        dim3 grid(WROWS, B_USERS);               // 52 rows: 50 data + 2 pad
        hist_kernel<<<grid, 96>>>(tokens, emb);
    }
    conv_mma_kernel<<<B_USERS, 256, conv_smem>>>(b3, b4, b5, hb);
    fc_kernel<<<B_USERS / TB, 256>>>(x, root, f1b, f2b, out);
}